// round 16
// baseline (speedup 1.0000x reference)
#include <cuda_runtime.h>
#include <cstdint>

#define NNODES 50000
typedef unsigned long long ull;

// ---------------- scratch (__device__ globals; no allocation) ----------------
// g_acc layout: [cnt: N floats][s1: N*96][s2: N*48]  -> single memset target
__device__ float g_acc[(size_t)NNODES * (1 + 96 + 48)];
__device__ float g_xl [(size_t)NNODES * 96];   // x  @ w1_l.T
__device__ float g_h1 [(size_t)NNODES * 96];   // layer-1 self term (pre-relu)
__device__ float g_h1l[(size_t)NNODES * 48];   // z @ w2_l.T

// ---------------- atomics ----------------
__device__ __forceinline__ void red_add_v4(float4* p, float4 v) {
    asm volatile("red.global.add.v4.f32 [%0], {%1, %2, %3, %4};"
                 :: "l"(p), "f"(v.x), "f"(v.y), "f"(v.z), "f"(v.w) : "memory");
}
__device__ __forceinline__ void red_add_f(float* p, float v) {
    asm volatile("red.global.add.f32 [%0], %1;" :: "l"(p), "f"(v) : "memory");
}

// ---------------- f32x2 packed FMA (sm_103a; PTX-only) ----------------
__device__ __forceinline__ ull ffma2(ull a, ull b, ull c) {
    ull d;
    asm("fma.rn.f32x2 %0, %1, %2, %3;" : "=l"(d) : "l"(a), "l"(b), "l"(c));
    return d;
}

// ---------------- dual-output GEMM: k-pair FFMA2, native-layout weights -------
// Computes, for row r: outa[r][c] = sum_k z[r][k]*wl[c][k]         (c < OUT/2)
//                      outb[r][c'] = sum_k z[r][k]*wr[c'][k] + bias[c']
// where z = FUSE ? relu(aggs/cnt + xin) : xin.   Input dim fixed at 96.
// Tile: 32 rows/CTA, warp = 4 rows, lane owns cols {lane+32j, j<OUT/32}.
// f32x2 lanes run along k (even/odd partials); epilogue adds lo+hi.
// Rows padded to 98 floats in smem: conflict-free LDS64, even (8B-aligned).
template<int OUT, bool FUSE>
__global__ void __launch_bounds__(256, OUT == 96 ? 4 : 2)
gemm_k(const float* __restrict__ xin, const float* __restrict__ aggs,
       const float* __restrict__ cnt,
       const float* __restrict__ wl, const float* __restrict__ wr,
       const float* __restrict__ bias,
       float* __restrict__ outa, float* __restrict__ outb, int nrows) {
    constexpr int C    = OUT / 32;
    constexpr int HALF = OUT / 2;
    extern __shared__ float sm[];
    float* wTs = sm;                 // OUT rows x 96 (pad 98), native [o][k]
    float* xs  = sm + OUT * 98;      // 32 rows x 96 (pad 98)
    const int tid = threadIdx.x;

    // stage weights (straight copy; rows < HALF from wl, rest from wr)
    for (int idx = tid; idx < OUT * 48; idx += 256) {
        int o = idx / 48, t = idx % 48;
        const float* src = (o < HALF) ? (wl + (size_t)o * 96)
                                      : (wr + (size_t)(o - HALF) * 96);
        *(float2*)(wTs + o * 98 + 2 * t) = *(const float2*)(src + 2 * t);
    }

    // stage input rows (optionally fused: z = relu(aggs*inv_cnt + xin))
    const int row0 = blockIdx.x * 32;
    for (int idx = tid; idx < 32 * 48; idx += 256) {
        int r = idx / 48, t = idx % 48;
        int row = row0 + r;
        float2 v = make_float2(0.f, 0.f);
        if (row < nrows) {
            if (FUSE) {
                float inv = 1.0f / fmaxf(__ldg(&cnt[row]), 1.0f);
                float2 s = __ldg((const float2*)(aggs + (size_t)row * 96) + t);
                float2 h = __ldg((const float2*)(xin + (size_t)row * 96) + t);
                v.x = fmaxf(fmaf(s.x, inv, h.x), 0.f);
                v.y = fmaxf(fmaf(s.y, inv, h.y), 0.f);
            } else {
                v = __ldg((const float2*)(xin + (size_t)row * 96) + t);
            }
        }
        *(float2*)(xs + r * 98 + 2 * t) = v;
    }
    __syncthreads();

    const int warp = tid >> 5, lane = tid & 31;
    const int rb = warp * 4;
    const float* xbase = xs + rb * 98;
    const float* wbase = wTs + lane * 98;

    ull acc[4][C];
#pragma unroll
    for (int m = 0; m < 4; m++)
#pragma unroll
        for (int j = 0; j < C; j++) acc[m][j] = 0ull;   // = (+0.f, +0.f)

#pragma unroll 2
    for (int k = 0; k < 96; k += 2) {
        ull xv[4], wv[C];
#pragma unroll
        for (int m = 0; m < 4; m++)
            xv[m] = *(const ull*)(xbase + m * 98 + k);          // broadcast LDS64
#pragma unroll
        for (int j = 0; j < C; j++)
            wv[j] = *(const ull*)(wbase + j * 32 * 98 + k);     // per-lane LDS64
#pragma unroll
        for (int m = 0; m < 4; m++)
#pragma unroll
            for (int j = 0; j < C; j++)
                acc[m][j] = ffma2(xv[m], wv[j], acc[m][j]);
    }

#pragma unroll
    for (int m = 0; m < 4; m++) {
        int row = row0 + rb + m;
        if (row >= nrows) break;
#pragma unroll
        for (int j = 0; j < C; j++) {
            float2 p = *(float2*)&acc[m][j];
            float v = p.x + p.y;
            int c = lane + 32 * j;
            if (c < HALF) outa[(size_t)row * HALF + c] = v;
            else          outb[(size_t)row * HALF + (c - HALF)] =
                              v + __ldg(&bias[c - HALF]);
        }
    }
}

// ---------------- edge scatter (warp-cooperative, vec4 red) — R5 exact -------
// CHUNKS = row float4 count (24 for 96 dims, 12 for 48). EPI = edges/iteration.
template<int CHUNKS, int EPI, bool COUNT>
__global__ void scatter_k(const int* __restrict__ ei, int E,
                          const float* __restrict__ feat, float* __restrict__ accv,
                          float* __restrict__ cnt) {
    int gw   = (blockIdx.x * blockDim.x + threadIdx.x) >> 5;
    int lane = threadIdx.x & 31;
    int base = gw * 32;
    if (base >= E) return;
    int nv = E - base; if (nv > 32) nv = 32;

    int s = 0, d = 0;
    if (lane < nv) {
        s = ei[base + lane];          // src row
        d = ei[E + base + lane];      // dst row
    }
    const int  sub    = lane / CHUNKS;
    const int  ch     = lane % CHUNKS;
    const bool active = lane < EPI * CHUNKS;
    const float4* f4 = (const float4*)feat;
    float4*       a4 = (float4*)accv;

    for (int j = 0; j < nv; j += EPI) {
        int jj = active ? (j + sub) : j;
        bool ok = jj < nv;
        int ss = __shfl_sync(0xffffffffu, s, jj & 31);
        int dd = __shfl_sync(0xffffffffu, d, jj & 31);
        if (active && ok) {
            float4 v = __ldg(f4 + (size_t)ss * CHUNKS + ch);
            red_add_v4(a4 + (size_t)dd * CHUNKS + ch, v);
        }
        if (COUNT && lane == EPI * CHUNKS && ok)
            red_add_f(cnt + dd, 1.0f);
    }
}

// ---------------- finalize layer 2 ----------------
__global__ void fin2_k(float* __restrict__ out, int n) {  // n = N*12
    int idx = blockIdx.x * blockDim.x + threadIdx.x;
    if (idx >= n) return;
    int i = idx / 12;
    float inv = 1.0f / fmaxf(g_acc[i], 1.0f);
    const float4* s2 = (const float4*)(g_acc + (size_t)NNODES * 97);
    float4 s = s2[idx];
    float4 o = ((float4*)out)[idx];
    o.x = fmaf(s.x, inv, o.x);
    o.y = fmaf(s.y, inv, o.y);
    o.z = fmaf(s.z, inv, o.z);
    o.w = fmaf(s.w, inv, o.w);
    ((float4*)out)[idx] = o;
}

// ---------------- launch ----------------
extern "C" void kernel_launch(void* const* d_in, const int* in_sizes, int n_in,
                              void* d_out, int out_size) {
    const float* x   = (const float*)d_in[0];
    const int*   ei  = (const int*)d_in[1];     // int32 (JAX x64 disabled)
    const float* w1l = (const float*)d_in[2];
    const float* b1  = (const float*)d_in[3];
    const float* w1r = (const float*)d_in[4];
    const float* w2l = (const float*)d_in[5];
    const float* b2  = (const float*)d_in[6];
    const float* w2r = (const float*)d_in[7];
    float*       out = (float*)d_out;

    const int N = in_sizes[0] / 96;     // 50000
    const int E = in_sizes[1] / 2;      // 800000

    void *p_acc, *p_xl, *p_h1, *p_h1l;
    cudaGetSymbolAddress(&p_acc, g_acc);
    cudaGetSymbolAddress(&p_xl,  g_xl);
    cudaGetSymbolAddress(&p_h1,  g_h1);
    cudaGetSymbolAddress(&p_h1l, g_h1l);

    float* cnt = (float*)p_acc;
    float* s1  = cnt + NNODES;
    float* s2  = cnt + (size_t)NNODES * 97;

    const int smem192 = (192 * 98 + 32 * 98) * 4;   // 87808 B
    const int smem96  = (96 * 98 + 32 * 98) * 4;    // 50176 B

    static bool attr_done = false;
    if (!attr_done) {
        cudaFuncSetAttribute(gemm_k<192, false>,
                             cudaFuncAttributeMaxDynamicSharedMemorySize, smem192);
        cudaFuncSetAttribute(gemm_k<96, true>,
                             cudaFuncAttributeMaxDynamicSharedMemorySize, smem96);
        attr_done = true;
    }

    // zero cnt | s1 | s2 in one memset node
    cudaMemsetAsync(p_acc, 0, sizeof(float) * (size_t)NNODES * 145, 0);

    const int ntiles      = (N + 31) / 32;
    const int edge_warps  = (E + 31) / 32;
    const int edge_blocks = (edge_warps + 7) / 8;

    // layer 1: xl = x @ w1_l.T ; h1 = x @ w1_r.T + b1  (self term)
    gemm_k<192, false><<<ntiles, 256, smem192>>>(
        x, nullptr, nullptr, w1l, w1r, b1, (float*)p_xl, (float*)p_h1, N);

    // s1 += xl[src] per edge; cnt[dst] += 1
    scatter_k<24, 1, true><<<edge_blocks, 256>>>(ei, E, (const float*)p_xl, s1, cnt);

    // layer 2 (fused fin1 staging): z = relu(s1/cnt + h1)
    // h1l = z @ w2_l.T ; out = z @ w2_r.T + b2
    gemm_k<96, true><<<ntiles, 256, smem96>>>(
        (const float*)p_h1, s1, cnt, w2l, w2r, b2, (float*)p_h1l, out, N);

    // s2 += h1l[src] per edge
    scatter_k<12, 2, false><<<edge_blocks, 256>>>(ei, E, (const float*)p_h1l, s2, nullptr);

    // out += s2/cnt
    fin2_k<<<(N * 12 + 255) / 256, 256>>>(out, N * 12);
}